// round 13
// baseline (speedup 1.0000x reference)
#include <cuda_runtime.h>
#include <cuda_bf16.h>

// NuclearLossFunc: loss = sum(x^2) / (B*C), x: (32,64,256,256) fp32
// = 134,217,728 elements = 512 MiB read. HBM-bound reduction.
//
// R13: champion R6 config (592x512 single wave, fused last-block
// finalize, acq_rel election — 80.58us kernel) with exactly ONE change:
// loads via __ldcg (L1-bypass, cache at L2). Streaming data never
// reuses L1; skipping the L1 fill removes per-wavefront L1tex work.
// Long-long indexing kept verbatim (address codegen controls ptxas's
// software pipeline; every prior regression traced to perturbing it).
// Deterministic: fixed trees, final accumulate in double.

#define NBLOCKS  592            // 148 SMs * 4 CTAs -> one wave
#define NTHREADS 512

__device__ double       g_partials[NBLOCKS];
__device__ unsigned int g_count;   // zero-initialized at module load

__global__ __launch_bounds__(NTHREADS) void sqsum_fused_kernel(
    const float4* __restrict__ in, long long n4,
    float* __restrict__ out, float scale)
{
    const int lane = threadIdx.x & 31;
    const int wid  = threadIdx.x >> 5;
    __shared__ double wd[NTHREADS / 32];
    __shared__ bool   s_is_last;

    // ---- hot loop: R6 verbatim except __ldcg ----
    float s0 = 0.f, s1 = 0.f, s2 = 0.f, s3 = 0.f;
    long long idx    = (long long)blockIdx.x * blockDim.x + threadIdx.x;
    long long stride = (long long)gridDim.x * blockDim.x;

    for (long long i = idx; i < n4; i += stride) {
        float4 v = __ldcg(in + i);
        s0 = fmaf(v.x, v.x, s0);
        s1 = fmaf(v.y, v.y, s1);
        s2 = fmaf(v.z, v.z, s2);
        s3 = fmaf(v.w, v.w, s3);
    }
    double acc = (double)((s0 + s1) + (s2 + s3));

    // ---- block reduce (double, fixed tree) ----
    #pragma unroll
    for (int o = 16; o > 0; o >>= 1)
        acc += __shfl_xor_sync(0xffffffffu, acc, o);

    if (lane == 0) wd[wid] = acc;
    __syncthreads();

    if (wid == 0) {
        acc = (lane < NTHREADS / 32) ? wd[lane] : 0.0;
        #pragma unroll
        for (int o = 16; o > 0; o >>= 1)
            acc += __shfl_xor_sync(0xffffffffu, acc, o);
        if (lane == 0) g_partials[blockIdx.x] = acc;   // released by acq_rel
    }

    // ---- last-block election: one acq_rel atomic, no fence ----
    if (threadIdx.x == 0) {
        unsigned int ticket;
        asm volatile("atom.add.acq_rel.gpu.u32 %0, [%1], 1;"
                     : "=r"(ticket) : "l"(&g_count) : "memory");
        s_is_last = (ticket == (unsigned int)(gridDim.x - 1));
    }
    __syncthreads();
    if (!s_is_last) return;

    // ---- last block: reduce 592 doubles (deterministic fixed tree) ----
    double dsum = 0.0;
    for (int p = threadIdx.x; p < NBLOCKS; p += NTHREADS)
        dsum += g_partials[p];

    #pragma unroll
    for (int o = 16; o > 0; o >>= 1)
        dsum += __shfl_xor_sync(0xffffffffu, dsum, o);

    if (lane == 0) wd[wid] = dsum;
    __syncthreads();

    if (wid == 0) {
        dsum = (lane < NTHREADS / 32) ? wd[lane] : 0.0;
        #pragma unroll
        for (int o = 16; o > 0; o >>= 1)
            dsum += __shfl_xor_sync(0xffffffffu, dsum, o);
        if (lane == 0) {
            out[0] = (float)(dsum * (double)scale);
            g_count = 0;  // reset for graph replay
        }
    }
}

extern "C" void kernel_launch(void* const* d_in, const int* in_sizes, int n_in,
                              void* d_out, int out_size)
{
    const float* x = (const float*)d_in[0];
    long long n  = (long long)in_sizes[0];    // 134,217,728, divisible by 4
    long long n4 = n >> 2;

    // B*C = n / (256*256) = 2048
    float scale = 1.0f / (float)(n / (256LL * 256LL));

    sqsum_fused_kernel<<<NBLOCKS, NTHREADS>>>((const float4*)x, n4,
                                              (float*)d_out, scale);
}

// round 14
// speedup vs baseline: 1.0691x; 1.0691x over previous
#include <cuda_runtime.h>
#include <cuda_bf16.h>

// NuclearLossFunc: loss = sum(x^2) / (B*C), x: (32,64,256,256) fp32
// = 134,217,728 elements = 512 MiB read. Pure HBM-bound reduction.
//
// FINAL (R6 champion, reconfirmed): fused single kernel, single wave
// (148 SMs x 4 CTAs x 512 thr = 592 CTAs, 2048 thr/SM, exactly 32
// regs/thread — the residency knife-edge every regression traced to).
// Static grid-stride float4 loop (measured 7.87 TB/s while DRAM busy;
// DRAM-active ~68.2us is invariant across all 13 explored variants —
// scheduler, TMA, addressing, cache-op changes are all neutral or
// negative). Last-block-done election via one atom.add.acq_rel.gpu
// (release: same-thread partial store; acquire: last block's reads).
// Deterministic: fixed reduction trees, final accumulate in double.

#define NBLOCKS  592            // 148 SMs * 4 CTAs -> exactly one wave
#define NTHREADS 512

__device__ float        g_partials[NBLOCKS];
__device__ unsigned int g_count;   // zero-initialized at module load

__global__ __launch_bounds__(NTHREADS) void sqsum_fused_kernel(
    const float4* __restrict__ in, long long n4,
    float* __restrict__ out, float scale)
{
    const int lane = threadIdx.x & 31;
    const int wid  = threadIdx.x >> 5;
    __shared__ float ws[NTHREADS / 32];
    __shared__ bool  s_is_last;

    // ---- hot loop: DO NOT TOUCH (measured best; 32 regs, full occ) ----
    float s0 = 0.f, s1 = 0.f, s2 = 0.f, s3 = 0.f;
    long long idx    = (long long)blockIdx.x * blockDim.x + threadIdx.x;
    long long stride = (long long)gridDim.x * blockDim.x;

    for (long long i = idx; i < n4; i += stride) {
        float4 v = in[i];
        s0 = fmaf(v.x, v.x, s0);
        s1 = fmaf(v.y, v.y, s1);
        s2 = fmaf(v.z, v.z, s2);
        s3 = fmaf(v.w, v.w, s3);
    }
    float s = (s0 + s1) + (s2 + s3);

    #pragma unroll
    for (int o = 16; o > 0; o >>= 1)
        s += __shfl_xor_sync(0xffffffffu, s, o);

    if (lane == 0) ws[wid] = s;
    __syncthreads();

    if (wid == 0) {
        s = (lane < NTHREADS / 32) ? ws[lane] : 0.f;
        #pragma unroll
        for (int o = 16; o > 0; o >>= 1)
            s += __shfl_xor_sync(0xffffffffu, s, o);
        if (lane == 0) g_partials[blockIdx.x] = s;   // released by atomic below
    }

    // ---- election: one acq_rel atomic, no fence ----
    if (threadIdx.x == 0) {
        unsigned int ticket;
        asm volatile("atom.add.acq_rel.gpu.u32 %0, [%1], 1;"
                     : "=r"(ticket) : "l"(&g_count) : "memory");
        s_is_last = (ticket == (unsigned int)(gridDim.x - 1));
    }
    __syncthreads();
    if (!s_is_last) return;

    // ---- last block: reduce 592 partials in double (deterministic) ----
    __shared__ double wd[NTHREADS / 32];
    double d = 0.0;
    for (int p = threadIdx.x; p < NBLOCKS; p += NTHREADS)
        d += (double)g_partials[p];

    #pragma unroll
    for (int o = 16; o > 0; o >>= 1)
        d += __shfl_xor_sync(0xffffffffu, d, o);

    if (lane == 0) wd[wid] = d;
    __syncthreads();

    if (wid == 0) {
        d = (lane < NTHREADS / 32) ? wd[lane] : 0.0;
        #pragma unroll
        for (int o = 16; o > 0; o >>= 1)
            d += __shfl_xor_sync(0xffffffffu, d, o);
        if (lane == 0) {
            out[0] = (float)(d * (double)scale);
            g_count = 0;  // reset for graph replay
        }
    }
}

extern "C" void kernel_launch(void* const* d_in, const int* in_sizes, int n_in,
                              void* d_out, int out_size)
{
    const float* x = (const float*)d_in[0];
    long long n = (long long)in_sizes[0];     // 134217728, divisible by 4
    long long n4 = n >> 2;

    // B*C = n / (256*256) = 2048
    float scale = 1.0f / (float)(n / (256LL * 256LL));

    sqsum_fused_kernel<<<NBLOCKS, NTHREADS>>>((const float4*)x, n4,
                                              (float*)d_out, scale);
}